// round 1
// baseline (speedup 1.0000x reference)
#include <cuda_runtime.h>
#include <cuda_bf16.h>
#include <math.h>

// Problem constants
#define NTOK   (32*1024)   // B*N = 32768 rows
#define DIM    768
#define HID    192

// ---------------- scratch (static device allocations; no cudaMalloc) --------
__device__ float g_Q1[(size_t)NTOK*DIM];
__device__ float g_K1[(size_t)NTOK*DIM];
__device__ float g_V1[(size_t)NTOK*DIM];
__device__ float g_Q2[(size_t)NTOK*DIM];
__device__ float g_K2[(size_t)NTOK*DIM];
__device__ float g_V2[(size_t)NTOK*DIM];
__device__ float g_Pa1[(size_t)NTOK*HID];
__device__ float g_Pb1[(size_t)NTOK*HID];
__device__ float g_Pa2[(size_t)NTOK*HID];
__device__ float g_Pb2[(size_t)NTOK*HID];
__device__ float g_rel1[NTOK];
__device__ float g_rel2[NTOK];
__device__ float g_kb[DIM];

// ---------------- kb = noise @ Wk  (768-vector) ------------------------------
__global__ void kb_kernel(const float* __restrict__ noise,
                          const float* __restrict__ Wk,
                          float* __restrict__ kb) {
    int j = blockIdx.x * blockDim.x + threadIdx.x;
    if (j >= DIM) return;
    float acc = 0.f;
    #pragma unroll 4
    for (int k = 0; k < DIM; k++)
        acc += noise[k] * Wk[(size_t)k * DIM + j];
    kb[j] = acc;
}

// ---------------- SGEMM: C[M,N] = A[M,K] @ B[K,N], all row-major -------------
// M multiple of 128, K multiple of 16, N multiple of 4 (guards on N).
#define BM 128
#define BN 128
#define BK 16
#define TM 8
#define TN 8

__global__ __launch_bounds__(256)
void sgemm_kernel(const float* __restrict__ A, const float* __restrict__ B,
                  float* __restrict__ C, int M, int N, int K) {
    __shared__ float As[BK][BM];
    __shared__ float Bs[BK][BN];

    const int tid = threadIdx.x;
    const int block_row = blockIdx.y * BM;
    const int block_col = blockIdx.x * BN;

    const int tcol = (tid % (BN / TN)) * TN;   // 0..120 step 8
    const int trow = (tid / (BN / TN)) * TM;   // 0..120 step 8

    float acc[TM][TN];
    #pragma unroll
    for (int i = 0; i < TM; i++)
        #pragma unroll
        for (int j = 0; j < TN; j++) acc[i][j] = 0.f;

    for (int k0 = 0; k0 < K; k0 += BK) {
        // Load A tile (BM x BK), store transposed into As[k][m].
        #pragma unroll
        for (int l = 0; l < 2; l++) {
            int f  = tid + l * 256;        // 0..511 float4 slots
            int ar = f >> 2;               // row within tile (0..127)
            int ac = (f & 3) * 4;          // k-col (0,4,8,12)
            float4 v = *(const float4*)(A + (size_t)(block_row + ar) * K + k0 + ac);
            As[ac + 0][ar] = v.x;
            As[ac + 1][ar] = v.y;
            As[ac + 2][ar] = v.z;
            As[ac + 3][ar] = v.w;
        }
        // Load B tile (BK x BN) straight; zero-fill out-of-range columns.
        #pragma unroll
        for (int l = 0; l < 2; l++) {
            int f  = tid + l * 256;
            int br = f >> 5;               // 0..15
            int bc = (f & 31) * 4;         // 0..124
            int gcol = block_col + bc;
            float4 v = make_float4(0.f, 0.f, 0.f, 0.f);
            if (gcol < N)
                v = *(const float4*)(B + (size_t)(k0 + br) * N + gcol);
            *(float4*)&Bs[br][bc] = v;
        }
        __syncthreads();

        #pragma unroll
        for (int kk = 0; kk < BK; kk++) {
            float a[TM], b[TN];
            *(float4*)&a[0] = *(const float4*)&As[kk][trow];
            *(float4*)&a[4] = *(const float4*)&As[kk][trow + 4];
            *(float4*)&b[0] = *(const float4*)&Bs[kk][tcol];
            *(float4*)&b[4] = *(const float4*)&Bs[kk][tcol + 4];
            #pragma unroll
            for (int i = 0; i < TM; i++)
                #pragma unroll
                for (int j = 0; j < TN; j++)
                    acc[i][j] = fmaf(a[i], b[j], acc[i][j]);
        }
        __syncthreads();
    }

    #pragma unroll
    for (int i = 0; i < TM; i++) {
        int grow = block_row + trow + i;
        #pragma unroll
        for (int j = 0; j < TN; j += 4) {
            int gcol = block_col + tcol + j;
            if (gcol < N) {   // N multiple of 4 -> whole float4 valid iff first lane valid
                float4 v = make_float4(acc[i][j], acc[i][j+1], acc[i][j+2], acc[i][j+3]);
                *(float4*)(C + (size_t)grow * N + gcol) = v;
            }
        }
    }
}

// ---------------- relation gate: rel = sigmoid(gelu(Pa+Pb+b1) @ W2 + b2) -----
__global__ __launch_bounds__(256)
void rel_kernel(const float* __restrict__ Pa1, const float* __restrict__ Pb1,
                const float* __restrict__ Pa2, const float* __restrict__ Pb2,
                const float* __restrict__ b1,  const float* __restrict__ W2,
                const float* __restrict__ b2,
                float* __restrict__ rel1, float* __restrict__ rel2) {
    const int r = blockIdx.x;
    const int j = threadIdx.x;
    float t1 = 0.f, t2 = 0.f;
    if (j < HID) {
        float bb = b1[j], w = W2[j];
        float h1 = Pa1[(size_t)r * HID + j] + Pb2[(size_t)r * HID + j] + bb;
        float h2 = Pa2[(size_t)r * HID + j] + Pb1[(size_t)r * HID + j] + bb;
        // exact gelu: x * 0.5 * (1 + erf(x / sqrt(2)))
        h1 = 0.5f * h1 * (1.0f + erff(h1 * 0.7071067811865475f));
        h2 = 0.5f * h2 * (1.0f + erff(h2 * 0.7071067811865475f));
        t1 = h1 * w;
        t2 = h2 * w;
    }
    // block reduce (8 warps)
    #pragma unroll
    for (int o = 16; o > 0; o >>= 1) {
        t1 += __shfl_down_sync(0xffffffffu, t1, o);
        t2 += __shfl_down_sync(0xffffffffu, t2, o);
    }
    __shared__ float s1[8], s2[8];
    if ((threadIdx.x & 31) == 0) { s1[threadIdx.x >> 5] = t1; s2[threadIdx.x >> 5] = t2; }
    __syncthreads();
    if (threadIdx.x == 0) {
        float a = 0.f, b = 0.f;
        #pragma unroll
        for (int w = 0; w < 8; w++) { a += s1[w]; b += s2[w]; }
        float bias = b2[0];
        rel1[r] = 1.0f / (1.0f + expf(-(a + bias)));
        rel2[r] = 1.0f / (1.0f + expf(-(b + bias)));
    }
}

// ---------------- fusion epilogue: 2-key softmax + residual ------------------
__global__ __launch_bounds__(256)
void fuse_kernel(const float* __restrict__ x1, const float* __restrict__ x2,
                 const float* __restrict__ Q1, const float* __restrict__ K1,
                 const float* __restrict__ V1, const float* __restrict__ Q2,
                 const float* __restrict__ K2, const float* __restrict__ V2,
                 const float* __restrict__ kb, const float* __restrict__ rel1,
                 const float* __restrict__ rel2,
                 float* __restrict__ y1, float* __restrict__ y2) {
    const int r = blockIdx.x;
    const size_t base = (size_t)r * DIM;

    float s1 = 0.f, c1 = 0.f, s2 = 0.f, c2 = 0.f;
    for (int i = threadIdx.x; i < DIM; i += 256) {
        float q1 = Q1[base + i], q2 = Q2[base + i];
        float k1 = K1[base + i], k2 = K2[base + i];
        float kn = kb[i];
        s1 = fmaf(q1, k1 + kn, s1);
        c1 = fmaf(q1, k2, c1);
        s2 = fmaf(q2, k2 + kn, s2);
        c2 = fmaf(q2, k1, c2);
    }
    #pragma unroll
    for (int o = 16; o > 0; o >>= 1) {
        s1 += __shfl_down_sync(0xffffffffu, s1, o);
        c1 += __shfl_down_sync(0xffffffffu, c1, o);
        s2 += __shfl_down_sync(0xffffffffu, s2, o);
        c2 += __shfl_down_sync(0xffffffffu, c2, o);
    }
    __shared__ float sred[4][8];
    if ((threadIdx.x & 31) == 0) {
        int w = threadIdx.x >> 5;
        sred[0][w] = s1; sred[1][w] = c1; sred[2][w] = s2; sred[3][w] = c2;
    }
    __syncthreads();
    __shared__ float ws[4];
    if (threadIdx.x == 0) {
        float a0 = 0.f, a1 = 0.f, a2 = 0.f, a3 = 0.f;
        #pragma unroll
        for (int w = 0; w < 8; w++) {
            a0 += sred[0][w]; a1 += sred[1][w]; a2 += sred[2][w]; a3 += sred[3][w];
        }
        const float scale = 0.03608439182435161f;  // 768^-0.5
        // direction 1
        float d1s = a0 * scale;
        float d1c = a1 * scale * rel1[r];
        float m = fmaxf(d1s, d1c);
        float e0 = expf(d1s - m), e1 = expf(d1c - m);
        float inv = 1.0f / (e0 + e1);
        ws[0] = e0 * inv; ws[1] = e1 * inv;
        // direction 2
        float d2s = a2 * scale;
        float d2c = a3 * scale * rel2[r];
        m = fmaxf(d2s, d2c);
        e0 = expf(d2s - m); e1 = expf(d2c - m);
        inv = 1.0f / (e0 + e1);
        ws[2] = e0 * inv; ws[3] = e1 * inv;
    }
    __syncthreads();
    const float w10 = ws[0], w11 = ws[1], w20 = ws[2], w21 = ws[3];
    for (int i = threadIdx.x; i < DIM; i += 256) {
        float v1 = V1[base + i], v2 = V2[base + i];
        y1[base + i] = x1[base + i] + w10 * v1 + w11 * v2;
        y2[base + i] = x2[base + i] + w20 * v2 + w21 * v1;
    }
}

// ---------------- launch ------------------------------------------------------
static inline void launch_sgemm(const float* A, const float* B, float* C,
                                int M, int N, int K, cudaStream_t s) {
    dim3 grid((N + BN - 1) / BN, M / BM);
    sgemm_kernel<<<grid, 256, 0, s>>>(A, B, C, M, N, K);
}

extern "C" void kernel_launch(void* const* d_in, const int* in_sizes, int n_in,
                              void* d_out, int out_size) {
    const float* x1    = (const float*)d_in[0];
    const float* x2    = (const float*)d_in[1];
    const float* Wq    = (const float*)d_in[2];
    const float* Wk    = (const float*)d_in[3];
    const float* Wv    = (const float*)d_in[4];
    const float* noise = (const float*)d_in[5];
    const float* W1    = (const float*)d_in[6];
    const float* b1    = (const float*)d_in[7];
    const float* W2    = (const float*)d_in[8];
    const float* b2    = (const float*)d_in[9];

    float *Q1, *K1, *V1, *Q2, *K2, *V2, *Pa1, *Pb1, *Pa2, *Pb2, *rel1, *rel2, *kb;
    cudaGetSymbolAddress((void**)&Q1,  g_Q1);
    cudaGetSymbolAddress((void**)&K1,  g_K1);
    cudaGetSymbolAddress((void**)&V1,  g_V1);
    cudaGetSymbolAddress((void**)&Q2,  g_Q2);
    cudaGetSymbolAddress((void**)&K2,  g_K2);
    cudaGetSymbolAddress((void**)&V2,  g_V2);
    cudaGetSymbolAddress((void**)&Pa1, g_Pa1);
    cudaGetSymbolAddress((void**)&Pb1, g_Pb1);
    cudaGetSymbolAddress((void**)&Pa2, g_Pa2);
    cudaGetSymbolAddress((void**)&Pb2, g_Pb2);
    cudaGetSymbolAddress((void**)&rel1, g_rel1);
    cudaGetSymbolAddress((void**)&rel2, g_rel2);
    cudaGetSymbolAddress((void**)&kb,  g_kb);

    cudaStream_t s = 0;  // harness capture stream (legacy default maps into capture)

    // kb = noise @ Wk
    kb_kernel<<<3, 256, 0, s>>>(noise, Wk, kb);

    // Projections: 6 GEMMs 32768x768x768
    launch_sgemm(x1, Wq, Q1, NTOK, DIM, DIM, s);
    launch_sgemm(x1, Wk, K1, NTOK, DIM, DIM, s);
    launch_sgemm(x1, Wv, V1, NTOK, DIM, DIM, s);
    launch_sgemm(x2, Wq, Q2, NTOK, DIM, DIM, s);
    launch_sgemm(x2, Wk, K2, NTOK, DIM, DIM, s);
    launch_sgemm(x2, Wv, V2, NTOK, DIM, DIM, s);

    // MLP partials: x_i @ W1[:768], x_i @ W1[768:]  (W1 row-major [1536,192])
    const float* W1a = W1;
    const float* W1b = W1 + (size_t)DIM * HID;
    launch_sgemm(x1, W1a, Pa1, NTOK, HID, DIM, s);
    launch_sgemm(x1, W1b, Pb1, NTOK, HID, DIM, s);
    launch_sgemm(x2, W1a, Pa2, NTOK, HID, DIM, s);
    launch_sgemm(x2, W1b, Pb2, NTOK, HID, DIM, s);

    // Relation gates
    rel_kernel<<<NTOK, 256, 0, s>>>(Pa1, Pb1, Pa2, Pb2, b1, W2, b2, rel1, rel2);

    // Fusion epilogue -> y1, y2 (concatenated in d_out)
    float* y1 = (float*)d_out;
    float* y2 = y1 + (size_t)NTOK * DIM;
    fuse_kernel<<<NTOK, 256, 0, s>>>(x1, x2, Q1, K1, V1, Q2, K2, V2,
                                     kb, rel1, rel2, y1, y2);
}

// round 3
// speedup vs baseline: 3.6438x; 3.6438x over previous
#include <cuda_runtime.h>
#include <math.h>
#include <stdint.h>

// ---------------- problem constants ----------------
#define NTOK   (32*1024)        // B*N rows
#define DIM    768
#define HID    192
#define NC     (3*DIM + 2*HID)  // 2688 fused output cols: Q|K|V|Pa|Pb
#define NKT    (DIM/32)         // 24 k-tiles of 32 floats
#define STAGES 3

// smem tile: As[128][36] + Bs[128][36] floats per stage (pad 4 -> conflict-free frags)
#define TPAD        36
#define STAGE_FLOATS (2*128*TPAD)
#define SMEM_TOTAL   (STAGES*STAGE_FLOATS*4)

// ---------------- scratch ----------------
__device__ __align__(256) float g_Wcat[(size_t)NC*DIM];    // [2688,768] K-major, tf32-rounded
__device__ __align__(256) float g_X1[(size_t)NTOK*DIM];    // tf32-rounded x1
__device__ __align__(256) float g_X2[(size_t)NTOK*DIM];    // tf32-rounded x2
__device__ __align__(256) float g_C1[(size_t)NTOK*NC];
__device__ __align__(256) float g_C2[(size_t)NTOK*NC];
__device__ float g_rel1[NTOK];
__device__ float g_rel2[NTOK];
__device__ float g_kb[DIM];

// ---------------- helpers ----------------
__device__ __forceinline__ float tf32_rna(float x) {
    uint32_t u;
    asm("cvt.rna.tf32.f32 %0, %1;" : "=r"(u) : "f"(x));
    return __uint_as_float(u);
}
__device__ __forceinline__ void cp_async16(void* dst_smem, const void* src) {
    uint32_t a;
    asm("{ .reg .u64 t; cvta.to.shared.u64 t, %1; cvt.u32.u64 %0, t; }" : "=r"(a) : "l"(dst_smem));
    asm volatile("cp.async.cg.shared.global [%0], [%1], 16;" :: "r"(a), "l"(src));
}
#define CP_COMMIT()  asm volatile("cp.async.commit_group;" ::: "memory")
#define CP_WAIT(n)   asm volatile("cp.async.wait_group %0;" :: "n"(n) : "memory")

__device__ __forceinline__ void mma_tf32(float* c, const uint32_t* a, const uint32_t* b) {
    asm volatile("mma.sync.aligned.m16n8k8.row.col.f32.tf32.tf32.f32 "
                 "{%0,%1,%2,%3}, {%4,%5,%6,%7}, {%8,%9}, {%0,%1,%2,%3};"
                 : "+f"(c[0]), "+f"(c[1]), "+f"(c[2]), "+f"(c[3])
                 : "r"(a[0]), "r"(a[1]), "r"(a[2]), "r"(a[3]), "r"(b[0]), "r"(b[1]));
}

// ---------------- tf32 mma GEMM: C[M,NT] = A[M,768] @ Bt[NT,768]^T ----------
// A, Bt pre-rounded to tf32. Grid: (NT/128, M/128). 256 threads.
__global__ void __launch_bounds__(256)
gemm_tf32_kernel(const float* __restrict__ A, const float* __restrict__ Bt,
                 float* __restrict__ C, int NT) {
    extern __shared__ float smem[];
    const int tid = threadIdx.x;
    const int lane = tid & 31, wid = tid >> 5;
    const int l4 = lane >> 2, lk = lane & 3;
    const int row0 = blockIdx.y * 128;
    const int col0 = blockIdx.x * 128;
    const int m0 = (wid & 3) * 32;   // warp tile 32x64
    const int n0 = (wid >> 2) * 64;

    // per-thread load assignment: 4 chunks of 16B for A, 4 for B, per stage
    const int lr = tid >> 3;          // 0..31 base row
    const int lseg = tid & 7;         // 16B segment within 128B row

    auto load_tile = [&](int kt, int s) {
        float* SA = smem + s * STAGE_FLOATS;
        float* SB = SA + 128 * TPAD;
        const int k0 = kt * 32;
        #pragma unroll
        for (int i = 0; i < 4; i++) {
            int r = lr + i * 32;
            cp_async16(SA + r * TPAD + lseg * 4,
                       A + (size_t)(row0 + r) * DIM + k0 + lseg * 4);
        }
        #pragma unroll
        for (int i = 0; i < 4; i++) {
            int r = lr + i * 32;
            cp_async16(SB + r * TPAD + lseg * 4,
                       Bt + (size_t)(col0 + r) * DIM + k0 + lseg * 4);
        }
        CP_COMMIT();
    };

    float acc[2][8][4];
    #pragma unroll
    for (int mt = 0; mt < 2; mt++)
        #pragma unroll
        for (int nt = 0; nt < 8; nt++)
            #pragma unroll
            for (int j = 0; j < 4; j++) acc[mt][nt][j] = 0.f;

    // prologue: 2 stages in flight
    load_tile(0, 0);
    load_tile(1, 1);

    for (int kt = 0; kt < NKT; kt++) {
        const int s = kt % STAGES;
        if (kt + 2 < NKT) { CP_WAIT(1); } else { CP_WAIT(0); }
        __syncthreads();
        if (kt + 2 < NKT) load_tile(kt + 2, (kt + 2) % STAGES);

        const float* SA = smem + s * STAGE_FLOATS;
        const float* SB = SA + 128 * TPAD;

        #pragma unroll
        for (int ks = 0; ks < 4; ks++) {
            const int kb = ks * 8 + lk;
            uint32_t a[2][4], b[8][2];
            #pragma unroll
            for (int mt = 0; mt < 2; mt++) {
                const float* p = SA + (m0 + mt * 16 + l4) * TPAD + kb;
                a[mt][0] = __float_as_uint(p[0]);
                a[mt][1] = __float_as_uint(p[8 * TPAD]);
                a[mt][2] = __float_as_uint(p[4]);
                a[mt][3] = __float_as_uint(p[8 * TPAD + 4]);
            }
            #pragma unroll
            for (int nt = 0; nt < 8; nt++) {
                const float* p = SB + (n0 + nt * 8 + l4) * TPAD + kb;
                b[nt][0] = __float_as_uint(p[0]);
                b[nt][1] = __float_as_uint(p[4]);
            }
            #pragma unroll
            for (int mt = 0; mt < 2; mt++)
                #pragma unroll
                for (int nt = 0; nt < 8; nt++)
                    mma_tf32(acc[mt][nt], a[mt], b[nt]);
        }
        __syncthreads();
    }

    // epilogue
    #pragma unroll
    for (int mt = 0; mt < 2; mt++) {
        const int r = row0 + m0 + mt * 16 + l4;
        #pragma unroll
        for (int nt = 0; nt < 8; nt++) {
            const int cc = col0 + n0 + nt * 8 + lk * 2;
            *(float2*)(C + (size_t)r * NT + cc) =
                make_float2(acc[mt][nt][0], acc[mt][nt][1]);
            *(float2*)(C + (size_t)(r + 8) * NT + cc) =
                make_float2(acc[mt][nt][2], acc[mt][nt][3]);
        }
    }
}

// ---------------- tf32 rounding pre-pass (vectorized, grid-stride) -----------
__global__ void round_tf32_kernel(float* __restrict__ dst, const float* __restrict__ src,
                                  int n4) {
    int i = blockIdx.x * blockDim.x + threadIdx.x;
    int stride = gridDim.x * blockDim.x;
    for (; i < n4; i += stride) {
        float4 v = ((const float4*)src)[i];
        v.x = tf32_rna(v.x); v.y = tf32_rna(v.y);
        v.z = tf32_rna(v.z); v.w = tf32_rna(v.w);
        ((float4*)dst)[i] = v;
    }
}

// ---------------- weight transpose + tf32 round: dst[c][r] = src[r][c] -------
__global__ void transpose_kernel(float* __restrict__ dst, const float* __restrict__ src,
                                 int src_rows, int src_cols, int src_stride) {
    __shared__ float tile[32][33];
    const int c0 = blockIdx.x * 32, r0 = blockIdx.y * 32;
    const int tx = threadIdx.x, ty = threadIdx.y;
    #pragma unroll
    for (int i = 0; i < 32; i += 8)
        tile[ty + i][tx] = src[(size_t)(r0 + ty + i) * src_stride + c0 + tx];
    __syncthreads();
    #pragma unroll
    for (int i = 0; i < 32; i += 8)
        dst[(size_t)(c0 + ty + i) * src_rows + r0 + tx] = tf32_rna(tile[tx][ty + i]);
}

// ---------------- kb = noise @ Wk (full fp32) ---------------------------------
__global__ void kb_kernel(const float* __restrict__ noise, const float* __restrict__ Wk,
                          float* __restrict__ kb) {
    int j = blockIdx.x * blockDim.x + threadIdx.x;
    if (j >= DIM) return;
    float acc = 0.f;
    #pragma unroll 4
    for (int k = 0; k < DIM; k++) acc += noise[k] * Wk[(size_t)k * DIM + j];
    kb[j] = acc;
}

// ---------------- relation gate ------------------------------------------------
__global__ void __launch_bounds__(256)
rel_kernel(const float* __restrict__ C1, const float* __restrict__ C2,
           const float* __restrict__ b1, const float* __restrict__ W2,
           const float* __restrict__ b2,
           float* __restrict__ rel1, float* __restrict__ rel2) {
    const int r = blockIdx.x;
    const int j = threadIdx.x;
    const size_t base = (size_t)r * NC;
    float t1 = 0.f, t2 = 0.f;
    if (j < HID) {
        float bb = b1[j], w = W2[j];
        float h1 = C1[base + 2304 + j] + C2[base + 2496 + j] + bb;
        float h2 = C2[base + 2304 + j] + C1[base + 2496 + j] + bb;
        h1 = 0.5f * h1 * (1.0f + erff(h1 * 0.7071067811865475f));
        h2 = 0.5f * h2 * (1.0f + erff(h2 * 0.7071067811865475f));
        t1 = h1 * w; t2 = h2 * w;
    }
    #pragma unroll
    for (int o = 16; o > 0; o >>= 1) {
        t1 += __shfl_down_sync(0xffffffffu, t1, o);
        t2 += __shfl_down_sync(0xffffffffu, t2, o);
    }
    __shared__ float s1[8], s2[8];
    if ((j & 31) == 0) { s1[j >> 5] = t1; s2[j >> 5] = t2; }
    __syncthreads();
    if (j == 0) {
        float a = 0.f, b = 0.f;
        #pragma unroll
        for (int w = 0; w < 8; w++) { a += s1[w]; b += s2[w]; }
        float bias = b2[0];
        rel1[r] = 1.0f / (1.0f + expf(-(a + bias)));
        rel2[r] = 1.0f / (1.0f + expf(-(b + bias)));
    }
}

// ---------------- fusion epilogue ----------------------------------------------
__global__ void __launch_bounds__(256)
fuse_kernel(const float* __restrict__ x1, const float* __restrict__ x2,
            const float* __restrict__ C1, const float* __restrict__ C2,
            const float* __restrict__ kb, const float* __restrict__ rel1,
            const float* __restrict__ rel2,
            float* __restrict__ y1, float* __restrict__ y2) {
    const int r = blockIdx.x;
    const size_t cb = (size_t)r * NC;
    const size_t xb = (size_t)r * DIM;

    float s1 = 0.f, c1 = 0.f, s2 = 0.f, c2 = 0.f;
    for (int i = threadIdx.x; i < DIM; i += 256) {
        float q1 = C1[cb + i],       q2 = C2[cb + i];
        float k1 = C1[cb + 768 + i], k2 = C2[cb + 768 + i];
        float kn = kb[i];
        s1 = fmaf(q1, k1 + kn, s1);
        c1 = fmaf(q1, k2, c1);
        s2 = fmaf(q2, k2 + kn, s2);
        c2 = fmaf(q2, k1, c2);
    }
    #pragma unroll
    for (int o = 16; o > 0; o >>= 1) {
        s1 += __shfl_down_sync(0xffffffffu, s1, o);
        c1 += __shfl_down_sync(0xffffffffu, c1, o);
        s2 += __shfl_down_sync(0xffffffffu, s2, o);
        c2 += __shfl_down_sync(0xffffffffu, c2, o);
    }
    __shared__ float sred[4][8];
    if ((threadIdx.x & 31) == 0) {
        int w = threadIdx.x >> 5;
        sred[0][w] = s1; sred[1][w] = c1; sred[2][w] = s2; sred[3][w] = c2;
    }
    __syncthreads();
    __shared__ float ws[4];
    if (threadIdx.x == 0) {
        float a0 = 0.f, a1 = 0.f, a2 = 0.f, a3 = 0.f;
        #pragma unroll
        for (int w = 0; w < 8; w++) { a0 += sred[0][w]; a1 += sred[1][w]; a2 += sred[2][w]; a3 += sred[3][w]; }
        const float scale = 0.03608439182435161f;  // 768^-0.5
        float d1s = a0 * scale, d1c = a1 * scale * rel1[r];
        float m = fmaxf(d1s, d1c);
        float e0 = expf(d1s - m), e1 = expf(d1c - m), inv = 1.0f / (e0 + e1);
        ws[0] = e0 * inv; ws[1] = e1 * inv;
        float d2s = a2 * scale, d2c = a3 * scale * rel2[r];
        m = fmaxf(d2s, d2c);
        e0 = expf(d2s - m); e1 = expf(d2c - m); inv = 1.0f / (e0 + e1);
        ws[2] = e0 * inv; ws[3] = e1 * inv;
    }
    __syncthreads();
    const float w10 = ws[0], w11 = ws[1], w20 = ws[2], w21 = ws[3];
    for (int i = threadIdx.x; i < DIM; i += 256) {
        float v1 = C1[cb + 1536 + i], v2 = C2[cb + 1536 + i];
        y1[xb + i] = x1[xb + i] + w10 * v1 + w11 * v2;
        y2[xb + i] = x2[xb + i] + w20 * v2 + w21 * v1;
    }
}

// ---------------- launch --------------------------------------------------------
extern "C" void kernel_launch(void* const* d_in, const int* in_sizes, int n_in,
                              void* d_out, int out_size) {
    const float* x1    = (const float*)d_in[0];
    const float* x2    = (const float*)d_in[1];
    const float* Wq    = (const float*)d_in[2];
    const float* Wk    = (const float*)d_in[3];
    const float* Wv    = (const float*)d_in[4];
    const float* noise = (const float*)d_in[5];
    const float* W1    = (const float*)d_in[6];
    const float* b1    = (const float*)d_in[7];
    const float* W2    = (const float*)d_in[8];
    const float* b2    = (const float*)d_in[9];

    float *Wcat, *X1, *X2, *C1, *C2, *rel1, *rel2, *kb;
    cudaGetSymbolAddress((void**)&Wcat, g_Wcat);
    cudaGetSymbolAddress((void**)&X1,   g_X1);
    cudaGetSymbolAddress((void**)&X2,   g_X2);
    cudaGetSymbolAddress((void**)&C1,   g_C1);
    cudaGetSymbolAddress((void**)&C2,   g_C2);
    cudaGetSymbolAddress((void**)&rel1, g_rel1);
    cudaGetSymbolAddress((void**)&rel2, g_rel2);
    cudaGetSymbolAddress((void**)&kb,   g_kb);

    static bool attr_done = false;
    if (!attr_done) {
        cudaFuncSetAttribute(gemm_tf32_kernel,
                             cudaFuncAttributeMaxDynamicSharedMemorySize, SMEM_TOTAL);
        attr_done = true;
    }

    cudaStream_t s = 0;

    // Wcat[2688,768] = WqT | WkT | WvT | W1aT | W1bT (tf32-rounded)
    dim3 tb(32, 8);
    transpose_kernel<<<dim3(24, 24), tb, 0, s>>>(Wcat + (size_t)0    * DIM, Wq, DIM, DIM, DIM);
    transpose_kernel<<<dim3(24, 24), tb, 0, s>>>(Wcat + (size_t)768  * DIM, Wk, DIM, DIM, DIM);
    transpose_kernel<<<dim3(24, 24), tb, 0, s>>>(Wcat + (size_t)1536 * DIM, Wv, DIM, DIM, DIM);
    transpose_kernel<<<dim3(6, 24),  tb, 0, s>>>(Wcat + (size_t)2304 * DIM, W1, DIM, HID, HID);
    transpose_kernel<<<dim3(6, 24),  tb, 0, s>>>(Wcat + (size_t)2496 * DIM, W1 + (size_t)DIM * HID, DIM, HID, HID);

    // tf32-round activations
    const int n4 = NTOK * DIM / 4;
    round_tf32_kernel<<<1184, 256, 0, s>>>(X1, x1, n4);
    round_tf32_kernel<<<1184, 256, 0, s>>>(X2, x2, n4);

    kb_kernel<<<3, 256, 0, s>>>(noise, Wk, kb);

    // Fused projections: C_i = X_i @ Wcat^T  (tf32 mma.sync)
    dim3 grid(NC / 128, NTOK / 128);
    gemm_tf32_kernel<<<grid, 256, SMEM_TOTAL, s>>>(X1, Wcat, C1, NC);
    gemm_tf32_kernel<<<grid, 256, SMEM_TOTAL, s>>>(X2, Wcat, C2, NC);

    rel_kernel<<<NTOK, 256, 0, s>>>(C1, C2, b1, W2, b2, rel1, rel2);

    float* y1 = (float*)d_out;
    float* y2 = y1 + (size_t)NTOK * DIM;
    fuse_kernel<<<NTOK, 256, 0, s>>>(x1, x2, C1, C2, kb, rel1, rel2, y1, y2);
}